// round 14
// baseline (speedup 1.0000x reference)
#include <cuda_runtime.h>
#include <cstdint>

// EmbeddingWithDropout:
//   out[t, :] = weight[x[t], :] * ((u[x[t]] >= 0.1f) ? (1.0f/0.9f) : 0.0f)
// x: int32 [131072], weight: f32 [100000,128], u: f32 [100000], out: f32 [131072,128]
//
// Floor-probe on the champion (R4: 16.864us, reproduced 2x).
// Established model: with streaming (.cs) stores the 51MB table stays
// L2-resident across graph replays and bench time == compulsory 67MB output
// drain to DRAM (~4TB/s write path). All MLP/occupancy/predication/persistence
// levers measured neutral or negative.
//
// R13: same cache-policy set as champion (.nc gathers, .cs stores) but with
// 256-bit (v8.b32) accesses — halves LSU wavefronts on gather AND store paths.
// Warp covers 8 tokens in 4 waves; per wave lanes 0-15 serve token base+2w,
// lanes 16-31 serve token base+2w+1; each lane moves one 32B segment
// (2 x 1024B contiguous per wave, fully coalesced).

#define WAVES 4  // tokens per warp = 2 * WAVES = 8

__device__ __forceinline__ void ldg_nc_v8(const float* p, float* v) {
    asm("ld.global.nc.v8.f32 {%0,%1,%2,%3,%4,%5,%6,%7}, [%8];"
        : "=f"(v[0]), "=f"(v[1]), "=f"(v[2]), "=f"(v[3]),
          "=f"(v[4]), "=f"(v[5]), "=f"(v[6]), "=f"(v[7])
        : "l"(p));
}

__device__ __forceinline__ void stg_cs_v8(float* p, const float* v) {
    asm volatile("st.global.cs.v8.f32 [%0], {%1,%2,%3,%4,%5,%6,%7,%8};"
                 :: "l"(p),
                    "f"(v[0]), "f"(v[1]), "f"(v[2]), "f"(v[3]),
                    "f"(v[4]), "f"(v[5]), "f"(v[6]), "f"(v[7])
                 : "memory");
}

__global__ void __launch_bounds__(256, 4)
embedding_dropout_kernel(const int* __restrict__ x,
                         const float* __restrict__ weight,   // [vocab,128]
                         const float* __restrict__ u,        // [vocab]
                         float* __restrict__ out,            // [n_tok,128]
                         int n_tok)
{
    const int gtid  = blockIdx.x * blockDim.x + threadIdx.x;
    const int warp  = gtid >> 5;
    const int lane  = threadIdx.x & 31;
    const int tpair = lane >> 4;     // which of the 2 tokens in this wave
    const int seg   = lane & 15;     // 32-byte segment within the 512B row
    const int base  = warp * (2 * WAVES);
    if (base >= n_tok) return;

    if (base + 2 * WAVES <= n_tok) {
        // ---- Wave 1: index loads (2 distinct addresses per warp-wave) ----
        int rows[WAVES];
        #pragma unroll
        for (int w = 0; w < WAVES; w++)
            rows[w] = __ldg(&x[base + 2 * w + tpair]);

        // ---- Wave 2: u-loads + 256-bit row gathers, all independent ----
        float uv[WAVES];
        float v[WAVES][8];
        #pragma unroll
        for (int w = 0; w < WAVES; w++) {
            uv[w] = __ldg(&u[rows[w]]);
            ldg_nc_v8(weight + (size_t)rows[w] * 128 + seg * 8, v[w]);
        }

        // ---- Scale + streaming 256-bit store ----
        #pragma unroll
        for (int w = 0; w < WAVES; w++) {
            const float keep = (uv[w] >= 0.1f) ? (1.0f / 0.9f) : 0.0f;
            #pragma unroll
            for (int j = 0; j < 8; j++)
                v[w][j] *= keep;
            stg_cs_v8(out + (size_t)(base + 2 * w + tpair) * 128 + seg * 8, v[w]);
        }
    } else {
        // ---- Tail path (float4 ops, per-token guard) ----
        #pragma unroll
        for (int w = 0; w < WAVES; w++) {
            const int tok = base + 2 * w + tpair;
            if (tok < n_tok) {
                const int row = __ldg(&x[tok]);
                const float keep = (__ldg(&u[row]) >= 0.1f) ? (1.0f / 0.9f) : 0.0f;
                const float4* wp = (const float4*)(weight + (size_t)row * 128 + seg * 8);
                float4 a = __ldg(wp);
                float4 b = __ldg(wp + 1);
                a.x *= keep; a.y *= keep; a.z *= keep; a.w *= keep;
                b.x *= keep; b.y *= keep; b.z *= keep; b.w *= keep;
                float4* op = (float4*)(out + (size_t)tok * 128 + seg * 8);
                __stcs(op,     a);
                __stcs(op + 1, b);
            }
        }
    }
}

extern "C" void kernel_launch(void* const* d_in, const int* in_sizes, int n_in,
                              void* d_out, int out_size)
{
    const int*   x      = (const int*)d_in[0];
    const float* weight = (const float*)d_in[1];
    const float* u      = (const float*)d_in[2];
    float*       out    = (float*)d_out;

    const int n_tok = in_sizes[0];                           // 131072
    const int threads = 256;                                 // 8 warps/block
    const int tok_per_block = (threads / 32) * (2 * WAVES);  // 64
    const int blocks = (n_tok + tok_per_block - 1) / tok_per_block;

    embedding_dropout_kernel<<<blocks, threads>>>(x, weight, u, out, n_tok);
}

// round 15
// speedup vs baseline: 1.1065x; 1.1065x over previous
#include <cuda_runtime.h>
#include <cstdint>

// EmbeddingWithDropout — FINAL (champion config, R4; 16.864us bench, reproduced 2x):
//   out[t, :] = weight[x[t], :] * ((u[x[t]] >= 0.1f) ? (1.0f/0.9f) : 0.0f)
// x: int32 [131072], weight: f32 [100000,128], u: f32 [100000], out: f32 [131072,128]
//
// One warp handles 8 tokens; each lane owns one float4 of the 128-wide row
// (32 x 16 B = 512 B, coalesced gather + store). Two batched memory waves:
// 8 index loads, then 8 u-loads + 8 row gathers issued together (MLP=16).
//
// Session findings (R3-R13, 11 measurements):
//  * Bench steady-state is a step function of the EFFECTIVE store cache policy:
//      __stcs(128-bit) 16.86us < evict_first 17.15 < plain 18.94 < wt 19.55.
//    __stcs makes the 67MB output stream the L2 eviction victim, so the 51MB
//    weight table stays L2-resident across graph replays; bench time then equals
//    the compulsory output drain to DRAM (67.1MB / 16.86us ~= 4TB/s write path).
//  * Neutral/negative within that policy: MLP 3..16, occupancy 49..74%,
//    instruction count +-2x (v8.b32), predicated gathers, persistent pipelining,
//    __ldcg gathers. 256-bit stores silently DROP the .cs operator (benches
//    land exactly on the plain-store 18.94us state) — so 128-bit __stcs it is.

#define TOK_PER_WARP 8

__global__ void __launch_bounds__(256, 4)
embedding_dropout_kernel(const int* __restrict__ x,
                         const float4* __restrict__ weight,   // [vocab*32] float4
                         const float* __restrict__ u,         // [vocab]
                         float4* __restrict__ out,            // [n_tok*32] float4
                         int n_tok)
{
    const int gtid = blockIdx.x * blockDim.x + threadIdx.x;
    const int warp = gtid >> 5;
    const int lane = threadIdx.x & 31;
    const int base = warp * TOK_PER_WARP;
    if (base >= n_tok) return;

    if (base + TOK_PER_WARP <= n_tok) {
        // ---- Wave 1: 8 independent index loads (uniform broadcast) ----
        int rows[TOK_PER_WARP];
        #pragma unroll
        for (int i = 0; i < TOK_PER_WARP; i++)
            rows[i] = __ldg(&x[base + i]);

        // ---- Wave 2: 8 u-loads + 8 row-gathers, all independent, issued together ----
        float uv[TOK_PER_WARP];
        float4 v[TOK_PER_WARP];
        #pragma unroll
        for (int i = 0; i < TOK_PER_WARP; i++) {
            uv[i] = __ldg(&u[rows[i]]);
            v[i]  = __ldg(&weight[(size_t)rows[i] * 32 + lane]);
        }

        // ---- Scale + streaming store (output = L2 eviction victim) ----
        #pragma unroll
        for (int i = 0; i < TOK_PER_WARP; i++) {
            const float keep = (uv[i] >= 0.1f) ? (1.0f / 0.9f) : 0.0f;
            v[i].x *= keep;
            v[i].y *= keep;
            v[i].z *= keep;
            v[i].w *= keep;
            __stcs(&out[(size_t)(base + i) * 32 + lane], v[i]);
        }
    } else {
        // ---- Tail path ----
        for (int i = 0; base + i < n_tok; i++) {
            const int row = __ldg(&x[base + i]);
            const float keep = (__ldg(&u[row]) >= 0.1f) ? (1.0f / 0.9f) : 0.0f;
            float4 v = __ldg(&weight[(size_t)row * 32 + lane]);
            v.x *= keep; v.y *= keep; v.z *= keep; v.w *= keep;
            __stcs(&out[(size_t)(base + i) * 32 + lane], v);
        }
    }
}

extern "C" void kernel_launch(void* const* d_in, const int* in_sizes, int n_in,
                              void* d_out, int out_size)
{
    const int*    x      = (const int*)d_in[0];
    const float4* weight = (const float4*)d_in[1];
    const float*  u      = (const float*)d_in[2];
    float4*       out    = (float4*)d_out;

    const int n_tok = in_sizes[0];                            // 131072
    const int threads = 256;                                  // 8 warps/block
    const int tok_per_block = (threads / 32) * TOK_PER_WARP;  // 64
    const int blocks = (n_tok + tok_per_block - 1) / tok_per_block;

    embedding_dropout_kernel<<<blocks, threads>>>(x, weight, u, out, n_tok);
}